// round 9
// baseline (speedup 1.0000x reference)
#include <cuda_runtime.h>
#include <stdint.h>

#define NPTS 500000
#define KK 27

// Scratch (allocation-free rule: __device__ globals)
__device__ uint32_t g_xt [NPTS * 128];  // tf32-truncated x (bit patterns)
__device__ uint32_t g_h0 [NPTS * 32];   // tf32 relu(x@W00+b00)
__device__ uint32_t g_h0c[NPTS * 32];   // tf32 relu(conv3(h0,W01)+b01)
__device__ uint32_t g_h1 [NPTS * 32];   // tf32 relu(conv3(x,W10)+b10)

// Permuted tf32 weights, fragment-ordered (R5 layout):
//   slot s = ((k*PAIRS + pr)*NTS + nt)*32 + lane, each slot = uint4
//   {W[k][pr*16+four][col], W[k][pr*16+four+4][col],
//    W[k][pr*16+four+8][col], W[k][pr*16+four+12][col]}
#define WP10_OFF 0
#define WP01_OFF 27648
#define WP11_OFF (27648 + 6912)
#define WP00_OFF (27648 + 6912 + 13824)
#define WP02_OFF (27648 + 6912 + 13824 + 1024)
__device__ uint4 g_wperm[27648 + 6912 + 13824 + 1024 + 512];

// ---------------------------------------------------------------------------
__device__ __forceinline__ uint32_t f2tf32(float v) {
    uint32_t r;
    asm("cvt.rna.tf32.f32 %0, %1;" : "=r"(r) : "f"(v));
    return r;
}

__device__ __forceinline__ void mma_16n8k8(float* c, uint32_t a0, uint32_t a1,
                                           uint32_t a2, uint32_t a3,
                                           uint32_t b0, uint32_t b1) {
    asm volatile(
        "mma.sync.aligned.m16n8k8.row.col.f32.tf32.tf32.f32 "
        "{%0,%1,%2,%3}, {%4,%5,%6,%7}, {%8,%9}, {%0,%1,%2,%3};"
        : "+f"(c[0]), "+f"(c[1]), "+f"(c[2]), "+f"(c[3])
        : "r"(a0), "r"(a1), "r"(a2), "r"(a3), "r"(b0), "r"(b1));
}

// ---------------------------------------------------------------------------
// x -> tf32 bit-pattern prepass (vectorized)
// ---------------------------------------------------------------------------
__global__ __launch_bounds__(256) void k_cvt_x(const float4* __restrict__ x,
                                               uint4* __restrict__ xt)
{
    const int i = blockIdx.x * 256 + threadIdx.x;
    if (i >= NPTS * 32) return;   // 64M floats / 4
    float4 v = x[i];
    uint4 q;
    q.x = f2tf32(v.x); q.y = f2tf32(v.y); q.z = f2tf32(v.z); q.w = f2tf32(v.w);
    xt[i] = q;
}

// ---------------------------------------------------------------------------
// Weight permutation prep (R5 layout, KKT taps).
// ---------------------------------------------------------------------------
template <int CIN, int COUT, int KKT>
__global__ void k_permW(const float* __restrict__ W, uint4* __restrict__ dst)
{
    const int PAIRS = CIN / 16, NTS = COUT / 8;
    const int total = KKT * PAIRS * NTS * 32;
    const int s = blockIdx.x * 256 + threadIdx.x;
    if (s >= total) return;
    const int lane = s & 31;
    int t = s >> 5;
    const int nt = t % NTS; t /= NTS;
    const int pr = t % PAIRS; t /= PAIRS;
    const int k = t;
    const int four = lane & 3, grp = lane >> 2;
    const int col = nt * 8 + grp;
    const int r0 = pr * 16 + four;
    const size_t base = (size_t)k * CIN * COUT + col;
    uint4 v;
    v.x = f2tf32(W[base + (size_t)(r0)      * COUT]);
    v.y = f2tf32(W[base + (size_t)(r0 + 4)  * COUT]);
    v.z = f2tf32(W[base + (size_t)(r0 + 8)  * COUT]);
    v.w = f2tf32(W[base + (size_t)(r0 + 12) * COUT]);
    dst[s] = v;
}

// ---------------------------------------------------------------------------
// Unified sparse-conv GEMM via mma.sync tf32.
// A operands are PRE-TRUNCATED tf32 bit patterns (uint32) -> raw loads, no CVT.
// Block: 256 threads = 8 warps; 256 points/block; warp owns 32 points.
// Single-sync double-buffered B staging (prefetch k+1 during k's MMAs).
// MODE 0: out[N,COUT] (uint32 tf32 bits) = tf32(relu(acc + b))
// MODE 1: out[N,128] f32 cols [64,128) = acc + b + x[:,64:128)   (COUT=64)
// MODE 2: out[N,128] f32 cols [0,64)   = acc + b + x[:,0:64)     (COUT=64)
// ---------------------------------------------------------------------------
template <int CIN, int COUT, int MODE, int GATHER>
__global__ __launch_bounds__(256) void k_conv_mma(
    const uint32_t* __restrict__ f, const int* __restrict__ nbr,
    const int* __restrict__ mask, const uint4* __restrict__ Wp,
    const float* __restrict__ b, const float* __restrict__ x,
    void* __restrict__ outv)
{
    const int PAIRS = CIN / 16, NTS = COUT / 8;
    const int KT = GATHER ? KK : 1;
    const int slabN = PAIRS * NTS * 32;        // uint4 per k
    const int NPER  = slabN / 256;             // uint4 per thread per slab
    __shared__ int   midx[GATHER ? 256 * KK : 8];
    __shared__ uint4 Bs4[2][PAIRS * NTS * 32 > 256 ? PAIRS * NTS * 32 : 256];
    __shared__ float bs[COUT];

    const int tid  = threadIdx.x;
    const int warp = tid >> 5;
    const int lane = tid & 31;
    const int grp  = lane >> 2;
    const int four = lane & 3;

    if (tid < COUT) bs[tid] = b[tid];

    const int pbase = blockIdx.x * 256;
    if (GATHER) {
        for (int i = tid; i < 256 * KK; i += 256) {
            const int p = pbase + i / KK;
            int v = -1;
            if (p < NPTS) {
                const size_t g = (size_t)p * KK + (i % KK);
                if (mask[g] != 0) v = nbr[g];
            }
            midx[i] = v;
        }
    }

    const int lr = warp * 32 + grp;            // rows lr+{0,8,16,24}

    float acc0[NTS][4], acc1[NTS][4];
#pragma unroll
    for (int nt = 0; nt < NTS; nt++)
#pragma unroll
        for (int j = 0; j < 4; j++) { acc0[nt][j] = 0.f; acc1[nt][j] = 0.f; }

    // prefetch slab k=0
    uint4 pre[NPER];
#pragma unroll
    for (int i = 0; i < NPER; i++) pre[i] = Wp[i * 256 + tid];

    for (int k = 0; k < KT; k++) {
        const int s = k & 1;
        // publish prefetched slab k into buffer s
#pragma unroll
        for (int i = 0; i < NPER; i++) Bs4[s][i * 256 + tid] = pre[i];
        __syncthreads();
        // prefetch slab k+1 (clamped)
        {
            const int kn = (k + 1 < KT) ? (k + 1) : k;
#pragma unroll
            for (int i = 0; i < NPER; i++)
                pre[i] = Wp[(size_t)kn * slabN + i * 256 + tid];
        }

        int idx[4];
#pragma unroll
        for (int r = 0; r < 4; r++) {
            if (GATHER) {
                idx[r] = midx[(lr + r * 8) * KK + k];
            } else {
                const int p = pbase + lr + r * 8;
                idx[r] = (p < NPTS) ? p : (NPTS - 1);   // clamp; store guarded later
            }
        }
        const uint32_t* rows[4];
#pragma unroll
        for (int r = 0; r < 4; r++)
            rows[r] = f + (size_t)(idx[r] < 0 ? 0 : idx[r]) * CIN;

#pragma unroll
        for (int pr = 0; pr < PAIRS; pr++) {
            uint32_t A[4][4];   // [row][elem: four, four+4, four+8, four+12]
#pragma unroll
            for (int r = 0; r < 4; r++) {
                if (!GATHER || idx[r] >= 0) {
                    const uint32_t* rp = rows[r] + pr * 16 + four;
                    A[r][0] = __ldg(rp);
                    A[r][1] = __ldg(rp + 4);
                    A[r][2] = __ldg(rp + 8);
                    A[r][3] = __ldg(rp + 12);
                } else {
                    A[r][0] = A[r][1] = A[r][2] = A[r][3] = 0u;
                }
            }
#pragma unroll
            for (int nt = 0; nt < NTS; nt++) {
                const uint4 B = Bs4[s][(pr * NTS + nt) * 32 + lane];
                mma_16n8k8(acc0[nt], A[0][0], A[1][0], A[0][1], A[1][1], B.x, B.y);
                mma_16n8k8(acc0[nt], A[0][2], A[1][2], A[0][3], A[1][3], B.z, B.w);
                mma_16n8k8(acc1[nt], A[2][0], A[3][0], A[2][1], A[3][1], B.x, B.y);
                mma_16n8k8(acc1[nt], A[2][2], A[3][2], A[2][3], A[3][3], B.z, B.w);
            }
        }
    }

    // epilogue: acc0 -> rows lr, lr+8 ; acc1 -> rows lr+16, lr+24
#pragma unroll
    for (int t = 0; t < 2; t++) {
#pragma unroll
        for (int half = 0; half < 2; half++) {
            const int p = pbase + lr + t * 16 + half * 8;
            if (p >= NPTS) continue;
#pragma unroll
            for (int nt = 0; nt < NTS; nt++) {
                const float c0 = (t == 0) ? acc0[nt][half * 2]     : acc1[nt][half * 2];
                const float c1 = (t == 0) ? acc0[nt][half * 2 + 1] : acc1[nt][half * 2 + 1];
                const int col = nt * 8 + 2 * four;
                if (MODE == 0) {
                    // store tf32-truncated bits (consumed as mma A operand)
                    uint2 v = {f2tf32(fmaxf(c0 + bs[col], 0.f)),
                               f2tf32(fmaxf(c1 + bs[col + 1], 0.f))};
                    *reinterpret_cast<uint2*>((uint32_t*)outv + (size_t)p * COUT + col) = v;
                } else {
                    const int oc = (MODE == 1) ? (64 + col) : col;
                    const size_t a = (size_t)p * 128 + oc;
                    float2 xr = *reinterpret_cast<const float2*>(x + a);
                    float2 v = {c0 + bs[col] + xr.x, c1 + bs[col + 1] + xr.y};
                    *reinterpret_cast<float2*>((float*)outv + a) = v;
                }
            }
        }
    }
}

// ---------------------------------------------------------------------------
extern "C" void kernel_launch(void* const* d_in, const int* in_sizes, int n_in,
                              void* d_out, int out_size)
{
    const float* x    = (const float*)d_in[0];
    const int*   nbr  = (const int*)  d_in[1];
    const int*   mask = (const int*)  d_in[2];   // bool -> int32 in harness
    const float* W00  = (const float*)d_in[3];
    const float* b00  = (const float*)d_in[4];
    const float* W01  = (const float*)d_in[5];
    const float* b01  = (const float*)d_in[6];
    const float* W02  = (const float*)d_in[7];
    const float* b02  = (const float*)d_in[8];
    const float* W10  = (const float*)d_in[9];
    const float* b10  = (const float*)d_in[10];
    const float* W11  = (const float*)d_in[11];
    const float* b11  = (const float*)d_in[12];
    float* out = (float*)d_out;

    uint32_t *xt, *h0, *h0c, *h1;
    uint4* wp;
    cudaGetSymbolAddress((void**)&xt,  g_xt);
    cudaGetSymbolAddress((void**)&h0,  g_h0);
    cudaGetSymbolAddress((void**)&h0c, g_h0c);
    cudaGetSymbolAddress((void**)&h1,  g_h1);
    cudaGetSymbolAddress((void**)&wp,  g_wperm);

    // prep: weight permutation (tiny) + x truncation (~90us)
    k_permW<128, 32, KK><<<(27648 + 255) / 256, 256>>>(W10, wp + WP10_OFF);
    k_permW< 32, 32, KK><<<( 6912 + 255) / 256, 256>>>(W01, wp + WP01_OFF);
    k_permW< 32, 64, KK><<<(13824 + 255) / 256, 256>>>(W11, wp + WP11_OFF);
    k_permW<128, 32,  1><<<( 1024 + 255) / 256, 256>>>(W00, wp + WP00_OFF);
    k_permW< 32, 64,  1><<<(  512 + 255) / 256, 256>>>(W02, wp + WP02_OFF);
    k_cvt_x<<<(NPTS * 32 + 255) / 256, 256>>>((const float4*)x, (uint4*)xt);

    const int blocks = (NPTS + 255) / 256;

    // branch 0: 1x1 -> relu  (tf32 out)
    k_conv_mma<128, 32, 0, 0><<<blocks, 256>>>(xt, nullptr, nullptr, wp + WP00_OFF, b00, nullptr, h0);
    // branch 1: 3x3 -> relu  (tf32 out)
    k_conv_mma<128, 32, 0, 1><<<blocks, 256>>>(xt, nbr, mask, wp + WP10_OFF, b10, nullptr, h1);
    // branch 0: 3x3 -> relu  (tf32 out)
    k_conv_mma<32, 32, 0, 1><<<blocks, 256>>>(h0, nbr, mask, wp + WP01_OFF, b01, nullptr, h0c);
    // branch 0 tail: 1x1 + bias + residual -> out[:, 0:64)
    k_conv_mma<32, 64, 2, 0><<<blocks, 256>>>(h0c, nullptr, nullptr, wp + WP02_OFF, b02, x, out);
    // branch 1 tail: 3x3 + bias + residual -> out[:, 64:128)
    k_conv_mma<32, 64, 1, 1><<<blocks, 256>>>(h1, nbr, mask, wp + WP11_OFF, b11, x, out);
}